// round 1
// baseline (speedup 1.0000x reference)
#include <cuda_runtime.h>
#include <cuda_bf16.h>
#include <cstdint>
#include <cstddef>

// Problem constants
#define Bb   2
#define Ss   2048
#define Hh   4096
#define NHh  32
#define HDd  128
#define QKVN (NHh * 3 * HDd)   // 12288
#define Mm   (Bb * Ss)         // 4096

// Scratch (allocation-free rule: __device__ globals)
__device__ float g_qkv[(size_t)Bb * Ss * NHh * 3 * HDd];  // [b,s,h,384]  (201 MB)
__device__ float g_attn[(size_t)Bb * Ss * NHh * HDd];     // [b,q,h,d]    (64 MB)

// ---------------------------------------------------------------------------
// Generic SGEMM with bias: C[M,N] = A[M,K] * B[K,N] + bias[N]
// BM=BN=128, BK=16, 256 threads, 8x8 register tile per thread.
// M,N multiples of 128; K multiple of 16. All pointers 16B aligned.
// ---------------------------------------------------------------------------
__global__ __launch_bounds__(256) void sgemm_bias_kernel(
    const float* __restrict__ A, const float* __restrict__ B,
    const float* __restrict__ bias, float* __restrict__ C,
    int M, int N, int K)
{
    constexpr int BM = 128, BN = 128, BK = 16;
    constexpr int ASTR = BM + 4;               // padded stride for As (bank spread)
    __shared__ float As[BK * ASTR];            // [k][m] transposed
    __shared__ float Bs[BK * BN];              // [k][n]

    const int tid = threadIdx.x;
    const int tx = tid & 15;                   // N direction
    const int ty = tid >> 4;                   // M direction
    const int brow = blockIdx.y * BM;
    const int bcol = blockIdx.x * BN;

    const float* Ab = A + (size_t)brow * K;
    const float* Bc = B + bcol;

    float acc[8][8];
    #pragma unroll
    for (int i = 0; i < 8; i++)
        #pragma unroll
        for (int j = 0; j < 8; j++) acc[i][j] = 0.0f;

    for (int k0 = 0; k0 < K; k0 += BK) {
        // Load A tile (128x16) transposed into As
        #pragma unroll
        for (int it = 0; it < 2; it++) {
            int idx = tid + it * 256;          // 0..511
            int r  = idx >> 2;                 // 0..127
            int c4 = idx & 3;                  // 0..3
            float4 v = *(const float4*)(Ab + (size_t)r * K + k0 + c4 * 4);
            As[(c4 * 4 + 0) * ASTR + r] = v.x;
            As[(c4 * 4 + 1) * ASTR + r] = v.y;
            As[(c4 * 4 + 2) * ASTR + r] = v.z;
            As[(c4 * 4 + 3) * ASTR + r] = v.w;
        }
        // Load B tile (16x128)
        #pragma unroll
        for (int it = 0; it < 2; it++) {
            int idx = tid + it * 256;
            int r  = idx >> 5;                 // 0..15
            int c4 = idx & 31;                 // 0..31
            *(float4*)(Bs + r * BN + c4 * 4) =
                *(const float4*)(Bc + (size_t)(k0 + r) * N + c4 * 4);
        }
        __syncthreads();

        #pragma unroll
        for (int kk = 0; kk < BK; kk++) {
            float a[8], bb[8];
            *(float4*)(a)      = *(const float4*)(As + kk * ASTR + ty * 8);
            *(float4*)(a + 4)  = *(const float4*)(As + kk * ASTR + ty * 8 + 4);
            *(float4*)(bb)     = *(const float4*)(Bs + kk * BN + tx * 8);
            *(float4*)(bb + 4) = *(const float4*)(Bs + kk * BN + tx * 8 + 4);
            #pragma unroll
            for (int i = 0; i < 8; i++)
                #pragma unroll
                for (int j = 0; j < 8; j++)
                    acc[i][j] += a[i] * bb[j];
        }
        __syncthreads();
    }

    #pragma unroll
    for (int i = 0; i < 8; i++) {
        int r = brow + ty * 8 + i;
        #pragma unroll
        for (int j = 0; j < 8; j += 4) {
            int c = bcol + tx * 8 + j;
            float4 bv = *(const float4*)(bias + c);
            float4 o;
            o.x = acc[i][j + 0] + bv.x;
            o.y = acc[i][j + 1] + bv.y;
            o.z = acc[i][j + 2] + bv.z;
            o.w = acc[i][j + 3] + bv.w;
            *(float4*)(C + (size_t)r * N + c) = o;
        }
    }
}

// ---------------------------------------------------------------------------
// Flash attention (fp32), causal + padding mask + alibi.
// One block = (64 q-rows) x (one head) x (one batch). 256 threads (16x16).
// qkv layout: [b, s, h, 384] with Q at [0:128), K at [128:256), V at [256:384).
// Output attn_out: [b, q, h, d].
// ---------------------------------------------------------------------------
#define FBQ 64
#define FBK 64
#define QSTR 68   // padded stride for transposed Q/K tiles ([d][q/k])
#define PSTR 68   // padded stride for P tile

#define FLASH_SMEM_FLOATS (128*QSTR /*Qt*/ + 128*QSTR /*Kt*/ + FBK*HDd /*Vs*/ + FBQ*PSTR /*Ps*/)

__global__ __launch_bounds__(256) void flash_kernel(
    const float* __restrict__ qkv, const float* __restrict__ alibi,
    const int* __restrict__ amask, float* __restrict__ attn_out)
{
    const int qt = blockIdx.x;     // q tile
    const int h  = blockIdx.y;
    const int b  = blockIdx.z;
    const int qb = qt * FBQ;

    const int tid = threadIdx.x;
    const int tx = tid & 15;       // 4 k-cols (S) / 8 d-cols (O)
    const int ty = tid >> 4;       // 4 q-rows

    extern __shared__ float sm[];
    float* Qt = sm;                       // [128][QSTR] transposed, pre-scaled
    float* Kt = Qt + 128 * QSTR;          // [128][QSTR] transposed
    float* Vs = Kt + 128 * QSTR;          // [64][128]
    float* Ps = Vs + FBK * HDd;           // [64][PSTR]

    const size_t row_stride = (size_t)NHh * 384;   // 12288
    const size_t qkv_b = (size_t)b * Ss * row_stride + (size_t)h * 384;
    const float* Qg = qkv + qkv_b + (size_t)qb * row_stride;
    const float* alib = alibi + ((size_t)b * NHh + h) * Ss;
    const int* amk = amask + (size_t)b * Ss;

    const float SCALE = 0.08838834764831845f;   // 1/sqrt(128)

    // Load Q tile transposed + scaled
    for (int i = tid; i < FBQ * 32; i += 256) {
        int q = i >> 5, d4 = i & 31;
        float4 v = *(const float4*)(Qg + (size_t)q * row_stride + d4 * 4);
        int d = d4 * 4;
        Qt[(d + 0) * QSTR + q] = v.x * SCALE;
        Qt[(d + 1) * QSTR + q] = v.y * SCALE;
        Qt[(d + 2) * QSTR + q] = v.z * SCALE;
        Qt[(d + 3) * QSTR + q] = v.w * SCALE;
    }

    float m[4], l[4], acc[4][8];
    #pragma unroll
    for (int i = 0; i < 4; i++) {
        m[i] = -1e30f; l[i] = 0.0f;
        #pragma unroll
        for (int j = 0; j < 8; j++) acc[i][j] = 0.0f;
    }

    const int nkt = qt + 1;   // causal: only tiles with kb <= qb
    for (int kt = 0; kt < nkt; kt++) {
        const int kb = kt * FBK;
        const float* Kg = qkv + qkv_b + (size_t)kb * row_stride + 128;
        const float* Vg = Kg + 128;

        __syncthreads();   // previous iter's reads of Kt/Vs/Ps complete
        for (int i = tid; i < FBK * 32; i += 256) {
            int k = i >> 5, d4 = i & 31;
            float4 v = *(const float4*)(Kg + (size_t)k * row_stride + d4 * 4);
            int d = d4 * 4;
            Kt[(d + 0) * QSTR + k] = v.x;
            Kt[(d + 1) * QSTR + k] = v.y;
            Kt[(d + 2) * QSTR + k] = v.z;
            Kt[(d + 3) * QSTR + k] = v.w;
            float4 w = *(const float4*)(Vg + (size_t)k * row_stride + d4 * 4);
            *(float4*)(Vs + k * HDd + d4 * 4) = w;
        }
        __syncthreads();

        // S = Q*K^T  (4x4 per thread)
        float s[4][4];
        #pragma unroll
        for (int i = 0; i < 4; i++)
            #pragma unroll
            for (int j = 0; j < 4; j++) s[i][j] = 0.0f;

        #pragma unroll 4
        for (int d = 0; d < 128; d++) {
            float a0[4], b0[4];
            *(float4*)a0 = *(const float4*)(Qt + d * QSTR + ty * 4);
            *(float4*)b0 = *(const float4*)(Kt + d * QSTR + tx * 4);
            #pragma unroll
            for (int i = 0; i < 4; i++)
                #pragma unroll
                for (int j = 0; j < 4; j++)
                    s[i][j] += a0[i] * b0[j];
        }

        // alibi + causal + padding mask
        #pragma unroll
        for (int j = 0; j < 4; j++) {
            int kg = kb + tx * 4 + j;
            float al = alib[kg];
            bool pad = amk[kg] > 0;
            #pragma unroll
            for (int i = 0; i < 4; i++) {
                int qg = qb + ty * 4 + i;
                s[i][j] = (pad && kg <= qg) ? (s[i][j] + al) : -1e30f;
            }
        }

        // online softmax update + stash P
        #pragma unroll
        for (int i = 0; i < 4; i++) {
            float rm = fmaxf(fmaxf(s[i][0], s[i][1]), fmaxf(s[i][2], s[i][3]));
            rm = fmaxf(rm, __shfl_xor_sync(0xffffffffu, rm, 1));
            rm = fmaxf(rm, __shfl_xor_sync(0xffffffffu, rm, 2));
            rm = fmaxf(rm, __shfl_xor_sync(0xffffffffu, rm, 4));
            rm = fmaxf(rm, __shfl_xor_sync(0xffffffffu, rm, 8));
            float mn = fmaxf(m[i], rm);
            float corr = __expf(m[i] - mn);
            float rs = 0.0f;
            #pragma unroll
            for (int j = 0; j < 4; j++) { s[i][j] = __expf(s[i][j] - mn); rs += s[i][j]; }
            rs += __shfl_xor_sync(0xffffffffu, rs, 1);
            rs += __shfl_xor_sync(0xffffffffu, rs, 2);
            rs += __shfl_xor_sync(0xffffffffu, rs, 4);
            rs += __shfl_xor_sync(0xffffffffu, rs, 8);
            l[i] = l[i] * corr + rs;
            m[i] = mn;
            #pragma unroll
            for (int j = 0; j < 8; j++) acc[i][j] *= corr;
            *(float4*)(Ps + (ty * 4 + i) * PSTR + tx * 4) = *(float4*)s[i];
        }
        __syncthreads();

        // O += P * V
        #pragma unroll 2
        for (int k = 0; k < FBK; k++) {
            float p0 = Ps[(ty * 4 + 0) * PSTR + k];
            float p1 = Ps[(ty * 4 + 1) * PSTR + k];
            float p2 = Ps[(ty * 4 + 2) * PSTR + k];
            float p3 = Ps[(ty * 4 + 3) * PSTR + k];
            float v0[4], v1[4];
            *(float4*)v0 = *(const float4*)(Vs + k * HDd + tx * 8);
            *(float4*)v1 = *(const float4*)(Vs + k * HDd + tx * 8 + 4);
            #pragma unroll
            for (int j = 0; j < 4; j++) {
                acc[0][j]     += p0 * v0[j];
                acc[0][j + 4] += p0 * v1[j];
                acc[1][j]     += p1 * v0[j];
                acc[1][j + 4] += p1 * v1[j];
                acc[2][j]     += p2 * v0[j];
                acc[2][j + 4] += p2 * v1[j];
                acc[3][j]     += p3 * v0[j];
                acc[3][j + 4] += p3 * v1[j];
            }
        }
    }

    // epilogue: O /= l, write [b, q, h, d]
    #pragma unroll
    for (int i = 0; i < 4; i++) {
        float inv = 1.0f / l[i];
        int qg = qb + ty * 4 + i;
        float* o = attn_out + ((size_t)(b * Ss + qg) * NHh + h) * HDd + tx * 8;
        float4 o0, o1;
        o0.x = acc[i][0] * inv; o0.y = acc[i][1] * inv;
        o0.z = acc[i][2] * inv; o0.w = acc[i][3] * inv;
        o1.x = acc[i][4] * inv; o1.y = acc[i][5] * inv;
        o1.z = acc[i][6] * inv; o1.w = acc[i][7] * inv;
        *(float4*)(o)     = o0;
        *(float4*)(o + 4) = o1;
    }
}

// ---------------------------------------------------------------------------
extern "C" void kernel_launch(void* const* d_in, const int* in_sizes, int n_in,
                              void* d_out, int out_size)
{
    const float* hidden = (const float*)d_in[0];   // [B,S,H]
    const float* alibi  = (const float*)d_in[1];   // [B,NH,1,S]
    const float* w_qkv  = (const float*)d_in[2];   // [H,NH,3*HD]
    const float* b_qkv  = (const float*)d_in[3];   // [NH,3*HD]
    const float* w_out  = (const float*)d_in[4];   // [NH,HD,H]
    const float* b_out  = (const float*)d_in[5];   // [H]
    const int*   amask  = (const int*)d_in[6];     // [B,S]
    float* out = (float*)d_out;                    // [B,S,H]

    float* qkv = nullptr;
    float* attn = nullptr;
    cudaGetSymbolAddress((void**)&qkv, g_qkv);
    cudaGetSymbolAddress((void**)&attn, g_attn);

    const int flash_smem = FLASH_SMEM_FLOATS * (int)sizeof(float);
    cudaFuncSetAttribute(flash_kernel,
                         cudaFuncAttributeMaxDynamicSharedMemorySize, flash_smem);

    // 1) fused QKV projection: [4096,4096] x [4096,12288] + bias
    sgemm_bias_kernel<<<dim3(QKVN / 128, Mm / 128), 256>>>(
        hidden, w_qkv, b_qkv, qkv, Mm, QKVN, Hh);

    // 2) flash attention with alibi + causal + padding mask
    flash_kernel<<<dim3(Ss / FBQ, NHh, Bb), 256, flash_smem>>>(
        qkv, alibi, amask, attn);

    // 3) output projection: [4096,4096] x [4096,4096] + bias
    sgemm_bias_kernel<<<dim3(Hh / 128, Mm / 128), 256>>>(
        attn, w_out, b_out, out, Mm, Hh, Hh);
}

// round 3
// speedup vs baseline: 2.6619x; 2.6619x over previous
#include <cuda_runtime.h>
#include <cuda_bf16.h>
#include <cstdint>
#include <cstddef>

// ---------------- problem constants ----------------
#define Bb   2
#define Ss   2048
#define Hh   4096
#define NHh  32
#define HDd  128
#define QKVN 12288            // NH * 3 * HD
#define Mm   4096             // B * S

// ---------------- scratch (__device__ globals; no allocs allowed) ----------
// fragment layouts:
//   A-frag [M/16][K/8][32 lanes][4 floats]
//   B-frag [N/8][K/8][32 lanes][2 floats]
__device__ float g_qkv [(size_t)Mm * QKVN];   // GEMM1 out, natural [M][N] (201 MB)
__device__ float g_attn[(size_t)Mm * Hh];     // flash out, A-frag layout (64 MB)
__device__ float g_hid [(size_t)Mm * Hh];     // hidden, A-frag layout    (64 MB)
__device__ float g_w1t [(size_t)QKVN * Hh];   // w_qkv, B-frag layout     (201 MB)
__device__ float g_w2t [(size_t)Hh * Hh];     // w_out, B-frag layout     (67 MB)

// ---------------- helpers ----------------
__device__ __forceinline__ uint32_t smem_u32(const void* p) {
    uint32_t a;
    asm("{ .reg .u64 t; cvta.to.shared.u64 t, %1; cvt.u32.u64 %0, t; }" : "=r"(a) : "l"(p));
    return a;
}
__device__ __forceinline__ float rna_tf32(float x) {
    uint32_t u;
    asm("cvt.rna.tf32.f32 %0, %1;" : "=r"(u) : "f"(x));
    return __uint_as_float(u);
}
#define CP_ASYNC16(dst, src) \
    asm volatile("cp.async.cg.shared.global [%0], [%1], 16;" :: "r"(dst), "l"(src))
#define CP_COMMIT() asm volatile("cp.async.commit_group;")

__device__ __forceinline__ void mma_tf32(float* d, const uint32_t* a, const uint32_t* b) {
    asm volatile(
        "mma.sync.aligned.m16n8k8.row.col.f32.tf32.tf32.f32 "
        "{%0,%1,%2,%3}, {%4,%5,%6,%7}, {%8,%9}, {%0,%1,%2,%3};"
        : "+f"(d[0]), "+f"(d[1]), "+f"(d[2]), "+f"(d[3])
        : "r"(a[0]), "r"(a[1]), "r"(a[2]), "r"(a[3]), "r"(b[0]), "r"(b[1]));
}

extern __shared__ float dynsm[];

// ---------------------------------------------------------------------------
// GEMM: C[M,N] = Af x Bf^T + bias.  Operands in fragment layout (tf32-rounded).
// CTA 128x128, 4 warps (64x64 each), BK=32 (4 k-atoms/stage), 3-stage cp.async.
// ---------------------------------------------------------------------------
#define NSTG 3
#define BKA 4                       // k-atoms (of 8) per stage
#define A_STG_BYTES (8 * BKA * 512) // 8 mi-atoms * BKA * 32 lanes * 16B = 16KB
#define B_STG_BYTES (16 * BKA * 256)// 16 ni-atoms * BKA * 32 lanes * 8B = 16KB
#define STG_BYTES (A_STG_BYTES + B_STG_BYTES)
#define GEMM_SMEM (NSTG * STG_BYTES)

__global__ __launch_bounds__(128) void gemm_mma_kernel(
    const float* __restrict__ Af, const float* __restrict__ Bf,
    const float* __restrict__ bias, float* __restrict__ C,
    int M, int N, int K)
{
    const int K8 = K >> 3;
    const int tid = threadIdx.x, lane = tid & 31, w = tid >> 5;
    const int wm = w >> 1, wn = w & 1;       // 2x2 warp grid

    // supertile remap (8 M-tiles per group) for L2 reuse
    const int NT = N >> 7;
    const int per = 8 * NT;
    const int gg = blockIdx.x / per, rr = blockIdx.x % per;
    const int mtile = gg * 8 + (rr & 7);
    const int ntile = rr >> 3;

    const float* Ag = Af + ((size_t)mtile * 8) * K8 * 128;   // mi0 = mtile*8
    const float* Bg = Bf + ((size_t)ntile * 16) * K8 * 64;   // ni0 = ntile*16

    const uint32_t sb = smem_u32(dynsm);

    // stage fill: A 1024 chunks of 16B, B 1024 chunks; 128 threads x 16 chunks
    auto fill = [&](int s, int kt0) {
        const uint32_t sA = sb + s * STG_BYTES;
        const uint32_t sB = sA + A_STG_BYTES;
        #pragma unroll
        for (int i = 0; i < 8; i++) {
            int c = tid + i * 128;                 // 0..1023
            int mi = c >> 7, r = c & 127;          // ki = r>>5, ln = r&31
            const float* g = Ag + ((size_t)mi * K8 + kt0 + (r >> 5)) * 128 + (r & 31) * 4;
            CP_ASYNC16(sA + c * 16, g);
        }
        #pragma unroll
        for (int i = 0; i < 8; i++) {
            int c = tid + i * 128;
            int ni = c >> 6, r = c & 63;           // ki = r>>4, q = r&15
            const float* g = Bg + ((size_t)ni * K8 + kt0 + (r >> 4)) * 64 + (r & 15) * 4;
            CP_ASYNC16(sB + c * 16, g);
        }
        CP_COMMIT();
    };

    float acc[4][8][4];
    #pragma unroll
    for (int a = 0; a < 4; a++)
        #pragma unroll
        for (int b = 0; b < 8; b++)
            #pragma unroll
            for (int e = 0; e < 4; e++) acc[a][b][e] = 0.0f;

    const int NITER = K8 / BKA;
    #pragma unroll
    for (int s = 0; s < NSTG; s++) fill(s, s * BKA);

    char* smp = (char*)dynsm;
    for (int it = 0; it < NITER; it++) {
        const int s = it % NSTG;
        char* sA = smp + s * STG_BYTES;
        char* sB = sA + A_STG_BYTES;

        asm volatile("cp.async.wait_group %0;" :: "n"(NSTG - 1));
        __syncthreads();

        #pragma unroll
        for (int ki = 0; ki < BKA; ki++) {
            uint32_t afr[4][4];
            #pragma unroll
            for (int a = 0; a < 4; a++) {
                float4 v = *(const float4*)(sA + (((wm * 4 + a) * BKA + ki) * 32 + lane) * 16);
                afr[a][0] = __float_as_uint(v.x); afr[a][1] = __float_as_uint(v.y);
                afr[a][2] = __float_as_uint(v.z); afr[a][3] = __float_as_uint(v.w);
            }
            uint32_t bfr[8][2];
            #pragma unroll
            for (int b = 0; b < 8; b++) {
                float2 v = *(const float2*)(sB + (((wn * 8 + b) * BKA + ki) * 32 + lane) * 8);
                bfr[b][0] = __float_as_uint(v.x); bfr[b][1] = __float_as_uint(v.y);
            }
            #pragma unroll
            for (int a = 0; a < 4; a++)
                #pragma unroll
                for (int b = 0; b < 8; b++)
                    mma_tf32(acc[a][b], afr[a], bfr[b]);
        }
        __syncthreads();

        if (it + NSTG < NITER) fill(s, (it + NSTG) * BKA);
        else CP_COMMIT();   // keep group accounting uniform
    }

    // epilogue: write C + bias (natural layout)
    const size_t row0 = (size_t)mtile * 128 + wm * 64 + (lane >> 2);
    const int col0 = ntile * 128 + wn * 64 + (lane & 3) * 2;
    #pragma unroll
    for (int a = 0; a < 4; a++) {
        #pragma unroll
        for (int b = 0; b < 8; b++) {
            int c = col0 + b * 8;
            float2 bv = *(const float2*)(bias + c);
            size_t r = row0 + a * 16;
            float2 o0; o0.x = acc[a][b][0] + bv.x; o0.y = acc[a][b][1] + bv.y;
            *(float2*)(C + r * N + c) = o0;
            float2 o1; o1.x = acc[a][b][2] + bv.x; o1.y = acc[a][b][3] + bv.y;
            *(float2*)(C + (r + 8) * N + c) = o1;
        }
    }
}

// ---------------------------------------------------------------------------
// prep: fragmentize + tf32-RNA round
// ---------------------------------------------------------------------------
// A-frag from row-major src[M][K]
__global__ __launch_bounds__(256) void frag_a_kernel(
    const float* __restrict__ src, float* __restrict__ dst, int K)
{
    __shared__ float t[32][33];
    const int k0 = blockIdx.x * 32, m0 = blockIdx.y * 32;
    const int tid = threadIdx.x;
    #pragma unroll
    for (int i = 0; i < 4; i++) {
        int r = (tid >> 5) + i * 8;
        t[r][tid & 31] = src[(size_t)(m0 + r) * K + k0 + (tid & 31)];
    }
    __syncthreads();
    const int w = tid >> 5, lane = tid & 31;
    const int mi_l = w >> 2, ki_l = w & 3;     // 2 mi x 4 ki
    float4 v;
    {
        int ml, kl;
        ml = mi_l * 16 + (lane >> 2);      kl = ki_l * 8 + (lane & 3);      v.x = rna_tf32(t[ml][kl]);
        ml = mi_l * 16 + 8 + (lane >> 2);                                    v.y = rna_tf32(t[ml][kl]);
        ml = mi_l * 16 + (lane >> 2);      kl = ki_l * 8 + 4 + (lane & 3);  v.z = rna_tf32(t[ml][kl]);
        ml = mi_l * 16 + 8 + (lane >> 2);                                    v.w = rna_tf32(t[ml][kl]);
    }
    size_t mi = (m0 >> 4) + mi_l, ki = (k0 >> 3) + ki_l;
    ((float4*)dst)[(mi * (K >> 3) + ki) * 32 + lane] = v;
}

// B-frag from row-major src[K][N] (weights): B[n][k] fragments
__global__ __launch_bounds__(256) void frag_b_kernel(
    const float* __restrict__ src, float* __restrict__ dst, int K, int N)
{
    __shared__ float t[32][33];
    const int n0 = blockIdx.x * 32, k0 = blockIdx.y * 32;
    const int tid = threadIdx.x;
    #pragma unroll
    for (int i = 0; i < 4; i++) {
        int r = (tid >> 5) + i * 8;
        t[r][tid & 31] = src[(size_t)(k0 + r) * N + n0 + (tid & 31)];
    }
    __syncthreads();
    const int w = tid >> 5, lane = tid & 31;
    #pragma unroll
    for (int fi = 0; fi < 2; fi++) {
        int f = w * 2 + fi;                    // 16 fragments: 4 ni x 4 ki
        int ni_l = f >> 2, ki_l = f & 3;
        float2 v;
        int nl = ni_l * 8 + (lane >> 2);
        int kl = ki_l * 8 + (lane & 3);
        v.x = rna_tf32(t[kl][nl]);
        v.y = rna_tf32(t[kl + 4][nl]);
        size_t ni = (n0 >> 3) + ni_l, ki = (k0 >> 3) + ki_l;
        ((float2*)dst)[(ni * (K >> 3) + ki) * 32 + lane] = v;
    }
}

// ---------------------------------------------------------------------------
// Flash attention (fp32), causal + padding + alibi. Output -> A-frag layout.
// ---------------------------------------------------------------------------
#define FBQ 64
#define FBK 64
#define QSTR 68
#define PSTR 68
#define FLASH_SMEM_FLOATS (128*QSTR + 128*QSTR + FBK*HDd + FBQ*PSTR)

__global__ __launch_bounds__(256) void flash_kernel(
    const float* __restrict__ qkv, const float* __restrict__ alibi,
    const int* __restrict__ amask, float* __restrict__ attn_out)
{
    const int qt = blockIdx.x;
    const int h  = blockIdx.y;
    const int b  = blockIdx.z;
    const int qb = qt * FBQ;

    const int tid = threadIdx.x;
    const int tx = tid & 15;
    const int ty = tid >> 4;

    float* sm = dynsm;
    float* Qt = sm;
    float* Kt = Qt + 128 * QSTR;
    float* Vs = Kt + 128 * QSTR;
    float* Ps = Vs + FBK * HDd;

    const size_t row_stride = (size_t)NHh * 384;
    const size_t qkv_b = (size_t)b * Ss * row_stride + (size_t)h * 384;
    const float* Qg = qkv + qkv_b + (size_t)qb * row_stride;
    const float* alib = alibi + ((size_t)b * NHh + h) * Ss;
    const int* amk = amask + (size_t)b * Ss;

    const float SCALE = 0.08838834764831845f;

    for (int i = tid; i < FBQ * 32; i += 256) {
        int q = i >> 5, d4 = i & 31;
        float4 v = *(const float4*)(Qg + (size_t)q * row_stride + d4 * 4);
        int d = d4 * 4;
        Qt[(d + 0) * QSTR + q] = v.x * SCALE;
        Qt[(d + 1) * QSTR + q] = v.y * SCALE;
        Qt[(d + 2) * QSTR + q] = v.z * SCALE;
        Qt[(d + 3) * QSTR + q] = v.w * SCALE;
    }

    float m[4], l[4], acc[4][8];
    #pragma unroll
    for (int i = 0; i < 4; i++) {
        m[i] = -1e30f; l[i] = 0.0f;
        #pragma unroll
        for (int j = 0; j < 8; j++) acc[i][j] = 0.0f;
    }

    const int nkt = qt + 1;
    for (int kt = 0; kt < nkt; kt++) {
        const int kb = kt * FBK;
        const float* Kg = qkv + qkv_b + (size_t)kb * row_stride + 128;
        const float* Vg = Kg + 128;

        __syncthreads();
        for (int i = tid; i < FBK * 32; i += 256) {
            int k = i >> 5, d4 = i & 31;
            float4 v = *(const float4*)(Kg + (size_t)k * row_stride + d4 * 4);
            int d = d4 * 4;
            Kt[(d + 0) * QSTR + k] = v.x;
            Kt[(d + 1) * QSTR + k] = v.y;
            Kt[(d + 2) * QSTR + k] = v.z;
            Kt[(d + 3) * QSTR + k] = v.w;
            float4 wv = *(const float4*)(Vg + (size_t)k * row_stride + d4 * 4);
            *(float4*)(Vs + k * HDd + d4 * 4) = wv;
        }
        __syncthreads();

        float s[4][4];
        #pragma unroll
        for (int i = 0; i < 4; i++)
            #pragma unroll
            for (int j = 0; j < 4; j++) s[i][j] = 0.0f;

        #pragma unroll 4
        for (int d = 0; d < 128; d++) {
            float a0[4], b0[4];
            *(float4*)a0 = *(const float4*)(Qt + d * QSTR + ty * 4);
            *(float4*)b0 = *(const float4*)(Kt + d * QSTR + tx * 4);
            #pragma unroll
            for (int i = 0; i < 4; i++)
                #pragma unroll
                for (int j = 0; j < 4; j++)
                    s[i][j] += a0[i] * b0[j];
        }

        #pragma unroll
        for (int j = 0; j < 4; j++) {
            int kg = kb + tx * 4 + j;
            float al = alib[kg];
            bool pad = amk[kg] > 0;
            #pragma unroll
            for (int i = 0; i < 4; i++) {
                int qg = qb + ty * 4 + i;
                s[i][j] = (pad && kg <= qg) ? (s[i][j] + al) : -1e30f;
            }
        }

        #pragma unroll
        for (int i = 0; i < 4; i++) {
            float rm = fmaxf(fmaxf(s[i][0], s[i][1]), fmaxf(s[i][2], s[i][3]));
            rm = fmaxf(rm, __shfl_xor_sync(0xffffffffu, rm, 1));
            rm = fmaxf(rm, __shfl_xor_sync(0xffffffffu, rm, 2));
            rm = fmaxf(rm, __shfl_xor_sync(0xffffffffu, rm, 4));
            rm = fmaxf(rm, __shfl_xor_sync(0xffffffffu, rm, 8));
            float mn = fmaxf(m[i], rm);
            float corr = __expf(m[i] - mn);
            float rs = 0.0f;
            #pragma unroll
            for (int j = 0; j < 4; j++) { s[i][j] = __expf(s[i][j] - mn); rs += s[i][j]; }
            rs += __shfl_xor_sync(0xffffffffu, rs, 1);
            rs += __shfl_xor_sync(0xffffffffu, rs, 2);
            rs += __shfl_xor_sync(0xffffffffu, rs, 4);
            rs += __shfl_xor_sync(0xffffffffu, rs, 8);
            l[i] = l[i] * corr + rs;
            m[i] = mn;
            #pragma unroll
            for (int j = 0; j < 8; j++) acc[i][j] *= corr;
            *(float4*)(Ps + (ty * 4 + i) * PSTR + tx * 4) = *(float4*)s[i];
        }
        __syncthreads();

        #pragma unroll 2
        for (int k = 0; k < FBK; k++) {
            float p0 = Ps[(ty * 4 + 0) * PSTR + k];
            float p1 = Ps[(ty * 4 + 1) * PSTR + k];
            float p2 = Ps[(ty * 4 + 2) * PSTR + k];
            float p3 = Ps[(ty * 4 + 3) * PSTR + k];
            float v0[4], v1[4];
            *(float4*)v0 = *(const float4*)(Vs + k * HDd + tx * 8);
            *(float4*)v1 = *(const float4*)(Vs + k * HDd + tx * 8 + 4);
            #pragma unroll
            for (int j = 0; j < 4; j++) {
                acc[0][j]     += p0 * v0[j];
                acc[0][j + 4] += p0 * v1[j];
                acc[1][j]     += p1 * v0[j];
                acc[1][j + 4] += p1 * v1[j];
                acc[2][j]     += p2 * v0[j];
                acc[2][j + 4] += p2 * v1[j];
                acc[3][j]     += p3 * v0[j];
                acc[3][j + 4] += p3 * v1[j];
            }
        }
    }

    // epilogue: O /= l, tf32-round, write A-frag layout for GEMM2 (K = NH*HD = 4096)
    #pragma unroll
    for (int i = 0; i < 4; i++) {
        float inv = 1.0f / l[i];
        int qg = qb + ty * 4 + i;
        int row = b * Ss + qg;                       // global M row
        int mi = row >> 4, r8 = row & 15;
        int laneb = (r8 & 7) * 4, eb = r8 >> 3;
        size_t ki = (size_t)h * 16 + tx;             // (h*128 + tx*8) / 8
        float* ob = attn_out + ((size_t)mi * 512 + ki) * 128;   // K8 = 512
        #pragma unroll
        for (int j = 0; j < 8; j++) {
            float v = rna_tf32(acc[i][j] * inv);
            ob[(laneb + (j & 3)) * 4 + eb + 2 * (j >> 2)] = v;
        }
    }
}

// ---------------------------------------------------------------------------
extern "C" void kernel_launch(void* const* d_in, const int* in_sizes, int n_in,
                              void* d_out, int out_size)
{
    const float* hidden = (const float*)d_in[0];
    const float* alibi  = (const float*)d_in[1];
    const float* w_qkv  = (const float*)d_in[2];
    const float* b_qkv  = (const float*)d_in[3];
    const float* w_out  = (const float*)d_in[4];
    const float* b_out  = (const float*)d_in[5];
    const int*   amask  = (const int*)d_in[6];
    float* out = (float*)d_out;

    float *qkv, *attn, *hid, *w1t, *w2t;
    cudaGetSymbolAddress((void**)&qkv,  g_qkv);
    cudaGetSymbolAddress((void**)&attn, g_attn);
    cudaGetSymbolAddress((void**)&hid,  g_hid);
    cudaGetSymbolAddress((void**)&w1t,  g_w1t);
    cudaGetSymbolAddress((void**)&w2t,  g_w2t);

    cudaFuncSetAttribute(gemm_mma_kernel,
                         cudaFuncAttributeMaxDynamicSharedMemorySize, GEMM_SMEM);
    const int flash_smem = FLASH_SMEM_FLOATS * (int)sizeof(float);
    cudaFuncSetAttribute(flash_kernel,
                         cudaFuncAttributeMaxDynamicSharedMemorySize, flash_smem);

    // prep: fragmentize + tf32-RNA round
    frag_a_kernel<<<dim3(Hh / 32, Mm / 32), 256>>>(hidden, hid, Hh);
    frag_b_kernel<<<dim3(QKVN / 32, Hh / 32), 256>>>(w_qkv, w1t, Hh, QKVN);
    frag_b_kernel<<<dim3(Hh / 32, Hh / 32), 256>>>(w_out, w2t, Hh, Hh);

    // 1) QKV projection (tensor cores, tf32 mma.sync)
    gemm_mma_kernel<<<(Mm / 128) * (QKVN / 128), 128, GEMM_SMEM>>>(
        hid, w1t, b_qkv, qkv, Mm, QKVN, Hh);

    // 2) flash attention
    flash_kernel<<<dim3(Ss / FBQ, NHh, Bb), 256, flash_smem>>>(
        qkv, alibi, amask, attn);

    // 3) output projection
    gemm_mma_kernel<<<(Mm / 128) * (Hh / 128), 128, GEMM_SMEM>>>(
        attn, w2t, b_out, out, Mm, Hh, Hh);
}

// round 4
// speedup vs baseline: 3.8968x; 1.4640x over previous
#include <cuda_runtime.h>
#include <cuda_bf16.h>
#include <cstdint>
#include <cstddef>

// ---------------- problem constants ----------------
#define Bb   2
#define Ss   2048
#define Hh   4096
#define NHh  32
#define HDd  128
#define QKVN 12288            // NH * 3 * HD
#define Mm   4096             // B * S

// ---------------- scratch (__device__ globals; no allocs allowed) ----------
// fragment layouts:
//   A-frag [M/16][K/8][32 lanes][4 floats]
//   B-frag [N/8][K/8][32 lanes][2 floats]
__device__ float g_qkv [(size_t)Mm * QKVN];   // GEMM1 out, natural [M][N] (201 MB)
__device__ float g_attn[(size_t)Mm * Hh];     // flash out, A-frag layout (64 MB)
__device__ float g_hid [(size_t)Mm * Hh];     // hidden, A-frag layout    (64 MB)
__device__ float g_w1t [(size_t)QKVN * Hh];   // w_qkv, B-frag layout     (201 MB)
__device__ float g_w2t [(size_t)Hh * Hh];     // w_out, B-frag layout     (67 MB)

// ---------------- helpers ----------------
__device__ __forceinline__ uint32_t smem_u32(const void* p) {
    uint32_t a;
    asm("{ .reg .u64 t; cvta.to.shared.u64 t, %1; cvt.u32.u64 %0, t; }" : "=r"(a) : "l"(p));
    return a;
}
__device__ __forceinline__ float rna_tf32(float x) {
    uint32_t u;
    asm("cvt.rna.tf32.f32 %0, %1;" : "=r"(u) : "f"(x));
    return __uint_as_float(u);
}
#define CP_ASYNC16(dst, src) \
    asm volatile("cp.async.cg.shared.global [%0], [%1], 16;" :: "r"(dst), "l"(src))
#define CP_COMMIT() asm volatile("cp.async.commit_group;")

__device__ __forceinline__ void mma_tf32(float* d, const uint32_t* a, const uint32_t* b) {
    asm volatile(
        "mma.sync.aligned.m16n8k8.row.col.f32.tf32.tf32.f32 "
        "{%0,%1,%2,%3}, {%4,%5,%6,%7}, {%8,%9}, {%0,%1,%2,%3};"
        : "+f"(d[0]), "+f"(d[1]), "+f"(d[2]), "+f"(d[3])
        : "r"(a[0]), "r"(a[1]), "r"(a[2]), "r"(a[3]), "r"(b[0]), "r"(b[1]));
}

// fast exp on the FMA pipe (no MUFU): exp(x) = 2^(x*log2e), deg-5 poly on [-.5,.5]
__device__ __forceinline__ float fexp(float x) {
    x = fmaxf(x, -80.0f);
    float y = x * 1.4426950408889634f;
    int   n = __float2int_rn(y);
    float f = y - (float)n;
    float p = 1.33335581e-3f;
    p = fmaf(p, f, 9.61812911e-3f);
    p = fmaf(p, f, 5.55041087e-2f);
    p = fmaf(p, f, 2.40226507e-1f);
    p = fmaf(p, f, 6.93147181e-1f);
    p = fmaf(p, f, 1.0f);
    return p * __int_as_float((n + 127) << 23);
}

extern __shared__ float dynsm[];

// ---------------------------------------------------------------------------
// GEMM: C[M,N] = Af x Bf^T + bias.  (unchanged from round 3: tensor=73%)
// ---------------------------------------------------------------------------
#define NSTG 3
#define BKA 4
#define A_STG_BYTES (8 * BKA * 512)
#define B_STG_BYTES (16 * BKA * 256)
#define STG_BYTES (A_STG_BYTES + B_STG_BYTES)
#define GEMM_SMEM (NSTG * STG_BYTES)

__global__ __launch_bounds__(128) void gemm_mma_kernel(
    const float* __restrict__ Af, const float* __restrict__ Bf,
    const float* __restrict__ bias, float* __restrict__ C,
    int M, int N, int K)
{
    const int K8 = K >> 3;
    const int tid = threadIdx.x, lane = tid & 31, w = tid >> 5;
    const int wm = w >> 1, wn = w & 1;

    const int NT = N >> 7;
    const int per = 8 * NT;
    const int gg = blockIdx.x / per, rr = blockIdx.x % per;
    const int mtile = gg * 8 + (rr & 7);
    const int ntile = rr >> 3;

    const float* Ag = Af + ((size_t)mtile * 8) * K8 * 128;
    const float* Bg = Bf + ((size_t)ntile * 16) * K8 * 64;

    const uint32_t sb = smem_u32(dynsm);

    auto fill = [&](int s, int kt0) {
        const uint32_t sA = sb + s * STG_BYTES;
        const uint32_t sB = sA + A_STG_BYTES;
        #pragma unroll
        for (int i = 0; i < 8; i++) {
            int c = tid + i * 128;
            int mi = c >> 7, r = c & 127;
            const float* g = Ag + ((size_t)mi * K8 + kt0 + (r >> 5)) * 128 + (r & 31) * 4;
            CP_ASYNC16(sA + c * 16, g);
        }
        #pragma unroll
        for (int i = 0; i < 8; i++) {
            int c = tid + i * 128;
            int ni = c >> 6, r = c & 63;
            const float* g = Bg + ((size_t)ni * K8 + kt0 + (r >> 4)) * 64 + (r & 15) * 4;
            CP_ASYNC16(sB + c * 16, g);
        }
        CP_COMMIT();
    };

    float acc[4][8][4];
    #pragma unroll
    for (int a = 0; a < 4; a++)
        #pragma unroll
        for (int b = 0; b < 8; b++)
            #pragma unroll
            for (int e = 0; e < 4; e++) acc[a][b][e] = 0.0f;

    const int NITER = K8 / BKA;
    #pragma unroll
    for (int s = 0; s < NSTG; s++) fill(s, s * BKA);

    char* smp = (char*)dynsm;
    for (int it = 0; it < NITER; it++) {
        const int s = it % NSTG;
        char* sA = smp + s * STG_BYTES;
        char* sB = sA + A_STG_BYTES;

        asm volatile("cp.async.wait_group %0;" :: "n"(NSTG - 1));
        __syncthreads();

        #pragma unroll
        for (int ki = 0; ki < BKA; ki++) {
            uint32_t afr[4][4];
            #pragma unroll
            for (int a = 0; a < 4; a++) {
                float4 v = *(const float4*)(sA + (((wm * 4 + a) * BKA + ki) * 32 + lane) * 16);
                afr[a][0] = __float_as_uint(v.x); afr[a][1] = __float_as_uint(v.y);
                afr[a][2] = __float_as_uint(v.z); afr[a][3] = __float_as_uint(v.w);
            }
            uint32_t bfr[8][2];
            #pragma unroll
            for (int b = 0; b < 8; b++) {
                float2 v = *(const float2*)(sB + (((wn * 8 + b) * BKA + ki) * 32 + lane) * 8);
                bfr[b][0] = __float_as_uint(v.x); bfr[b][1] = __float_as_uint(v.y);
            }
            #pragma unroll
            for (int a = 0; a < 4; a++)
                #pragma unroll
                for (int b = 0; b < 8; b++)
                    mma_tf32(acc[a][b], afr[a], bfr[b]);
        }
        __syncthreads();

        if (it + NSTG < NITER) fill(s, (it + NSTG) * BKA);
        else CP_COMMIT();
    }

    const size_t row0 = (size_t)mtile * 128 + wm * 64 + (lane >> 2);
    const int col0 = ntile * 128 + wn * 64 + (lane & 3) * 2;
    #pragma unroll
    for (int a = 0; a < 4; a++) {
        #pragma unroll
        for (int b = 0; b < 8; b++) {
            int c = col0 + b * 8;
            float2 bv = *(const float2*)(bias + c);
            size_t r = row0 + a * 16;
            float2 o0; o0.x = acc[a][b][0] + bv.x; o0.y = acc[a][b][1] + bv.y;
            *(float2*)(C + r * N + c) = o0;
            float2 o1; o1.x = acc[a][b][2] + bv.x; o1.y = acc[a][b][3] + bv.y;
            *(float2*)(C + (r + 8) * N + c) = o1;
        }
    }
}

// ---------------------------------------------------------------------------
// prep: fragmentize + tf32-RNA round (unchanged)
// ---------------------------------------------------------------------------
__global__ __launch_bounds__(256) void frag_a_kernel(
    const float* __restrict__ src, float* __restrict__ dst, int K)
{
    __shared__ float t[32][33];
    const int k0 = blockIdx.x * 32, m0 = blockIdx.y * 32;
    const int tid = threadIdx.x;
    #pragma unroll
    for (int i = 0; i < 4; i++) {
        int r = (tid >> 5) + i * 8;
        t[r][tid & 31] = src[(size_t)(m0 + r) * K + k0 + (tid & 31)];
    }
    __syncthreads();
    const int w = tid >> 5, lane = tid & 31;
    const int mi_l = w >> 2, ki_l = w & 3;
    float4 v;
    {
        int ml, kl;
        ml = mi_l * 16 + (lane >> 2);      kl = ki_l * 8 + (lane & 3);      v.x = rna_tf32(t[ml][kl]);
        ml = mi_l * 16 + 8 + (lane >> 2);                                    v.y = rna_tf32(t[ml][kl]);
        ml = mi_l * 16 + (lane >> 2);      kl = ki_l * 8 + 4 + (lane & 3);  v.z = rna_tf32(t[ml][kl]);
        ml = mi_l * 16 + 8 + (lane >> 2);                                    v.w = rna_tf32(t[ml][kl]);
    }
    size_t mi = (m0 >> 4) + mi_l, ki = (k0 >> 3) + ki_l;
    ((float4*)dst)[(mi * (K >> 3) + ki) * 32 + lane] = v;
}

__global__ __launch_bounds__(256) void frag_b_kernel(
    const float* __restrict__ src, float* __restrict__ dst, int K, int N)
{
    __shared__ float t[32][33];
    const int n0 = blockIdx.x * 32, k0 = blockIdx.y * 32;
    const int tid = threadIdx.x;
    #pragma unroll
    for (int i = 0; i < 4; i++) {
        int r = (tid >> 5) + i * 8;
        t[r][tid & 31] = src[(size_t)(k0 + r) * N + n0 + (tid & 31)];
    }
    __syncthreads();
    const int w = tid >> 5, lane = tid & 31;
    #pragma unroll
    for (int fi = 0; fi < 2; fi++) {
        int f = w * 2 + fi;
        int ni_l = f >> 2, ki_l = f & 3;
        float2 v;
        int nl = ni_l * 8 + (lane >> 2);
        int kl = ki_l * 8 + (lane & 3);
        v.x = rna_tf32(t[kl][nl]);
        v.y = rna_tf32(t[kl + 4][nl]);
        size_t ni = (n0 >> 3) + ni_l, ki = (k0 >> 3) + ki_l;
        ((float2*)dst)[(ni * (K >> 3) + ki) * 32 + lane] = v;
    }
}

// ---------------------------------------------------------------------------
// Flash attention on tensor cores (mma.sync tf32) + FFMA-pipe exp.
// CTA: 64 q-rows, 4 warps (one m16 atom each, all 64 keys). Output A-frag.
// SMEM (floats): Kf[8][16][32][2]=8192 | Vf[16][8][32][2]=8192
//                Pf[4][16][68]=4352    | sAl[64]
// Q staged via overlay at base ([64][132]); epilogue O overlay at base too.
// ---------------------------------------------------------------------------
#define F_KF   0
#define F_VF   8192
#define F_PF   16384
#define F_SAL  (F_PF + 4*16*68)           // 20736
#define FLASH2_SMEM_FLOATS (F_SAL + 64 + 16)
#define QS_STR 132

__global__ __launch_bounds__(128) void flash_mma_kernel(
    const float* __restrict__ qkv, const float* __restrict__ alibi,
    const int* __restrict__ amask, float* __restrict__ attn_out)
{
    const int qt = blockIdx.x, h = blockIdx.y, b = blockIdx.z;
    const int qb = qt * 64;
    const int tid = threadIdx.x, lane = tid & 31, w = tid >> 5;

    float* sm = dynsm;
    float* Kf = sm + F_KF;
    float* Vf = sm + F_VF;
    float* Pf = sm + F_PF + w * 16 * 68;
    float* sAl = sm + F_SAL;

    const size_t row_stride = (size_t)NHh * 384;
    const size_t qkv_b = (size_t)b * Ss * row_stride + (size_t)h * 384;
    const float* alib = alibi + ((size_t)b * NHh + h) * Ss;
    const int* amk = amask + (size_t)b * Ss;
    const float SCALE = 0.08838834764831845f;

    // ---- stage Q (scaled + RNA) into overlay, then lift A-frags to regs ----
    {
        const float* Qg = qkv + qkv_b + (size_t)qb * row_stride;
        #pragma unroll
        for (int i = 0; i < 16; i++) {
            int u = i * 128 + tid;              // 0..2047
            int r = u >> 5, c4 = u & 31;
            float4 v = *(const float4*)(Qg + (size_t)r * row_stride + c4 * 4);
            v.x = rna_tf32(v.x * SCALE); v.y = rna_tf32(v.y * SCALE);
            v.z = rna_tf32(v.z * SCALE); v.w = rna_tf32(v.w * SCALE);
            *(float4*)(sm + r * QS_STR + c4 * 4) = v;
        }
    }
    __syncthreads();

    uint32_t qf[16][4];
    {
        const int r0 = w * 16 + (lane >> 2), c = lane & 3;
        #pragma unroll
        for (int ka = 0; ka < 16; ka++) {
            qf[ka][0] = __float_as_uint(sm[r0 * QS_STR + ka * 8 + c]);
            qf[ka][1] = __float_as_uint(sm[(r0 + 8) * QS_STR + ka * 8 + c]);
            qf[ka][2] = __float_as_uint(sm[r0 * QS_STR + ka * 8 + c + 4]);
            qf[ka][3] = __float_as_uint(sm[(r0 + 8) * QS_STR + ka * 8 + c + 4]);
        }
    }

    float m0 = -1e29f, m1 = -1e29f, l0 = 0.0f, l1 = 0.0f;
    float acc[16][4];
    #pragma unroll
    for (int na = 0; na < 16; na++)
        #pragma unroll
        for (int e = 0; e < 4; e++) acc[na][e] = 0.0f;

    const int qg0 = qb + w * 16 + (lane >> 2);
    const int qg1 = qg0 + 8;

    for (int kt = 0; kt <= qt; kt++) {
        const int kb = kt * 64;
        const float* Kg = qkv + qkv_b + (size_t)kb * row_stride + 128;
        const float* Vg = Kg + 128;

        __syncthreads();    // prior tile's Kf/Vf reads done (also Q-frag reads)

        // K -> B-frag layout (n=key, k=d)
        #pragma unroll
        for (int i = 0; i < 8; i++) {
            int u = i * 128 + tid;              // 0..1023
            int k = u & 63, dg = u >> 6;        // dg: 0..15
            const float* rp = Kg + (size_t)k * row_stride + dg * 8;
            float4 a4 = *(const float4*)rp;
            float4 b4 = *(const float4*)(rp + 4);
            float* dst = Kf + (((k >> 3) * 16 + dg) * 32 + (k & 7) * 4) * 2;
            ((float2*)dst)[0] = make_float2(rna_tf32(a4.x), rna_tf32(b4.x));
            ((float2*)dst)[1] = make_float2(rna_tf32(a4.y), rna_tf32(b4.y));
            ((float2*)dst)[2] = make_float2(rna_tf32(a4.z), rna_tf32(b4.z));
            ((float2*)dst)[3] = make_float2(rna_tf32(a4.w), rna_tf32(b4.w));
        }
        // V -> B-frag layout (n=d, k=key)
        #pragma unroll
        for (int i = 0; i < 8; i++) {
            int u = i * 128 + tid;
            int k = u & 63, dg = u >> 6;
            const float* rp = Vg + (size_t)k * row_stride + dg * 8;
            float4 a4 = *(const float4*)rp;
            float4 b4 = *(const float4*)(rp + 4);
            const int e = (k & 7) >> 2;
            float* base = Vf + ((dg * 8 + (k >> 3)) * 32 + (k & 3)) * 2 + e;
            base[0 * 8] = rna_tf32(a4.x); base[1 * 8] = rna_tf32(a4.y);
            base[2 * 8] = rna_tf32(a4.z); base[3 * 8] = rna_tf32(a4.w);
            base[4 * 8] = rna_tf32(b4.x); base[5 * 8] = rna_tf32(b4.y);
            base[6 * 8] = rna_tf32(b4.z); base[7 * 8] = rna_tf32(b4.w);
        }
        if (tid < 64) {
            int kg = kb + tid;
            sAl[tid] = (amk[kg] > 0) ? alib[kg] : -1e30f;
        }
        __syncthreads();

        // ---- S = Q K^T ----
        float sfr[8][4];
        #pragma unroll
        for (int na = 0; na < 8; na++)
            #pragma unroll
            for (int e = 0; e < 4; e++) sfr[na][e] = 0.0f;

        #pragma unroll
        for (int ka = 0; ka < 16; ka++) {
            #pragma unroll
            for (int na = 0; na < 8; na++) {
                const uint32_t* b2 = (const uint32_t*)(Kf + ((na * 16 + ka) * 32 + lane) * 2);
                mma_tf32(sfr[na], qf[ka], b2);
            }
        }

        // ---- mask + alibi, online softmax ----
        const bool diag = (kt == qt);
        float tm0 = -1e30f, tm1 = -1e30f;
        #pragma unroll
        for (int na = 0; na < 8; na++) {
            int c0 = na * 8 + (lane & 3) * 2;
            int kg0 = kb + c0;
            float al0 = sAl[c0], al1 = sAl[c0 + 1];
            if (diag) {
                sfr[na][0] = (kg0     <= qg0) ? sfr[na][0] + al0 : -1e30f;
                sfr[na][1] = (kg0 + 1 <= qg0) ? sfr[na][1] + al1 : -1e30f;
                sfr[na][2] = (kg0     <= qg1) ? sfr[na][2] + al0 : -1e30f;
                sfr[na][3] = (kg0 + 1 <= qg1) ? sfr[na][3] + al1 : -1e30f;
            } else {
                sfr[na][0] += al0; sfr[na][1] += al1;
                sfr[na][2] += al0; sfr[na][3] += al1;
            }
            tm0 = fmaxf(tm0, fmaxf(sfr[na][0], sfr[na][1]));
            tm1 = fmaxf(tm1, fmaxf(sfr[na][2], sfr[na][3]));
        }
        tm0 = fmaxf(tm0, __shfl_xor_sync(0xffffffffu, tm0, 1));
        tm0 = fmaxf(tm0, __shfl_xor_sync(0xffffffffu, tm0, 2));
        tm1 = fmaxf(tm1, __shfl_xor_sync(0xffffffffu, tm1, 1));
        tm1 = fmaxf(tm1, __shfl_xor_sync(0xffffffffu, tm1, 2));

        float mn0 = fmaxf(m0, tm0), mn1 = fmaxf(m1, tm1);
        float corr0 = fexp(m0 - mn0), corr1 = fexp(m1 - mn1);

        float rs0 = 0.0f, rs1 = 0.0f;
        const int r0l = lane >> 2, cc = (lane & 3) * 2;
        #pragma unroll
        for (int na = 0; na < 8; na++) {
            float p0 = fexp(sfr[na][0] - mn0);
            float p1 = fexp(sfr[na][1] - mn0);
            float p2 = fexp(sfr[na][2] - mn1);
            float p3 = fexp(sfr[na][3] - mn1);
            rs0 += p0 + p1; rs1 += p2 + p3;
            *(float2*)(Pf + r0l * 68 + na * 8 + cc)       = make_float2(rna_tf32(p0), rna_tf32(p1));
            *(float2*)(Pf + (r0l + 8) * 68 + na * 8 + cc) = make_float2(rna_tf32(p2), rna_tf32(p3));
        }
        rs0 += __shfl_xor_sync(0xffffffffu, rs0, 1);
        rs0 += __shfl_xor_sync(0xffffffffu, rs0, 2);
        rs1 += __shfl_xor_sync(0xffffffffu, rs1, 1);
        rs1 += __shfl_xor_sync(0xffffffffu, rs1, 2);
        l0 = l0 * corr0 + rs0;  m0 = mn0;
        l1 = l1 * corr1 + rs1;  m1 = mn1;
        #pragma unroll
        for (int na = 0; na < 16; na++) {
            acc[na][0] *= corr0; acc[na][1] *= corr0;
            acc[na][2] *= corr1; acc[na][3] *= corr1;
        }
        __syncwarp();

        // ---- O += P V ----
        const int c = lane & 3;
        #pragma unroll
        for (int ka = 0; ka < 8; ka++) {
            uint32_t pa[4];
            pa[0] = __float_as_uint(Pf[r0l * 68 + ka * 8 + c]);
            pa[1] = __float_as_uint(Pf[(r0l + 8) * 68 + ka * 8 + c]);
            pa[2] = __float_as_uint(Pf[r0l * 68 + ka * 8 + c + 4]);
            pa[3] = __float_as_uint(Pf[(r0l + 8) * 68 + ka * 8 + c + 4]);
            #pragma unroll
            for (int na = 0; na < 16; na++) {
                const uint32_t* b2 = (const uint32_t*)(Vf + ((na * 8 + ka) * 32 + lane) * 2);
                mma_tf32(acc[na], pa, b2);
            }
        }
    }

    // ---- epilogue: O/l -> SMEM (C layout) -> A-frag -> gmem ----
    __syncthreads();
    {
        float inv0 = 1.0f / fmaxf(l0, 1e-30f);
        float inv1 = 1.0f / fmaxf(l1, 1e-30f);
        int r0 = w * 16 + (lane >> 2);
        #pragma unroll
        for (int na = 0; na < 16; na++) {
            int cc = na * 8 + (lane & 3) * 2;
            *(float2*)(sm + r0 * QS_STR + cc)       = make_float2(acc[na][0] * inv0, acc[na][1] * inv0);
            *(float2*)(sm + (r0 + 8) * QS_STR + cc) = make_float2(acc[na][2] * inv1, acc[na][3] * inv1);
        }
    }
    __syncwarp();
    {
        int r0 = w * 16 + (lane >> 2), c = lane & 3;
        size_t mi = (size_t)(b * Ss + qb + w * 16) >> 4;
        #pragma unroll
        for (int ka = 0; ka < 16; ka++) {
            float4 v;
            v.x = rna_tf32(sm[r0 * QS_STR + ka * 8 + c]);
            v.y = rna_tf32(sm[(r0 + 8) * QS_STR + ka * 8 + c]);
            v.z = rna_tf32(sm[r0 * QS_STR + ka * 8 + c + 4]);
            v.w = rna_tf32(sm[(r0 + 8) * QS_STR + ka * 8 + c + 4]);
            ((float4*)attn_out)[(mi * 512 + h * 16 + ka) * 32 + lane] = v;
        }
    }
}

// ---------------------------------------------------------------------------
extern "C" void kernel_launch(void* const* d_in, const int* in_sizes, int n_in,
                              void* d_out, int out_size)
{
    const float* hidden = (const float*)d_in[0];
    const float* alibi  = (const float*)d_in[1];
    const float* w_qkv  = (const float*)d_in[2];
    const float* b_qkv  = (const float*)d_in[3];
    const float* w_out  = (const float*)d_in[4];
    const float* b_out  = (const float*)d_in[5];
    const int*   amask  = (const int*)d_in[6];
    float* out = (float*)d_out;

    float *qkv, *attn, *hid, *w1t, *w2t;
    cudaGetSymbolAddress((void**)&qkv,  g_qkv);
    cudaGetSymbolAddress((void**)&attn, g_attn);
    cudaGetSymbolAddress((void**)&hid,  g_hid);
    cudaGetSymbolAddress((void**)&w1t,  g_w1t);
    cudaGetSymbolAddress((void**)&w2t,  g_w2t);

    cudaFuncSetAttribute(gemm_mma_kernel,
                         cudaFuncAttributeMaxDynamicSharedMemorySize, GEMM_SMEM);
    const int flash_smem = FLASH2_SMEM_FLOATS * (int)sizeof(float);
    cudaFuncSetAttribute(flash_mma_kernel,
                         cudaFuncAttributeMaxDynamicSharedMemorySize, flash_smem);

    // prep: fragmentize + tf32-RNA round
    frag_a_kernel<<<dim3(Hh / 32, Mm / 32), 256>>>(hidden, hid, Hh);
    frag_b_kernel<<<dim3(QKVN / 32, Hh / 32), 256>>>(w_qkv, w1t, Hh, QKVN);
    frag_b_kernel<<<dim3(Hh / 32, Hh / 32), 256>>>(w_out, w2t, Hh, Hh);

    // 1) QKV projection (tensor cores)
    gemm_mma_kernel<<<(Mm / 128) * (QKVN / 128), 128, GEMM_SMEM>>>(
        hid, w1t, b_qkv, qkv, Mm, QKVN, Hh);

    // 2) flash attention (tensor cores + FFMA exp)
    flash_mma_kernel<<<dim3(Ss / 64, NHh, Bb), 128, flash_smem>>>(
        qkv, alibi, amask, attn);

    // 3) output projection (tensor cores)
    gemm_mma_kernel<<<(Mm / 128) * (Hh / 128), 128, GEMM_SMEM>>>(
        attn, w2t, b_out, out, Mm, Hh, Hh);
}

// round 6
// speedup vs baseline: 5.8487x; 1.5009x over previous
#include <cuda_runtime.h>
#include <cuda_fp16.h>
#include <cuda_bf16.h>
#include <cstdint>
#include <cstddef>

// ---------------- problem constants ----------------
#define Bb   2
#define Ss   2048
#define Hh   4096
#define NHh  32
#define HDd  128
#define QKVN 12288            // NH * 3 * HD
#define Mm   4096             // B * S

// ---------------- scratch (__device__ globals; no allocs allowed) ----------
// half fragment layouts (m16n8k16):
//   A-frag [M/16][K/16][32 lanes][4 u32 = 8 halves]
//   B-frag [N/8][K/16][32 lanes][2 u32 = 4 halves]
__device__ float  g_qkv [(size_t)Mm * QKVN];   // GEMM1 out, natural (201 MB)
__device__ __half g_attn[(size_t)Mm * Hh];     // flash out, A-frag half (32 MB)
__device__ __half g_hid [(size_t)Mm * Hh];     // hidden, A-frag half    (32 MB)
__device__ __half g_w1t [(size_t)QKVN * Hh];   // w_qkv, B-frag half     (100 MB)
__device__ __half g_w2t [(size_t)Hh * Hh];     // w_out, B-frag half     (33 MB)

// ---------------- helpers ----------------
__device__ __forceinline__ uint32_t smem_u32(const void* p) {
    uint32_t a;
    asm("{ .reg .u64 t; cvta.to.shared.u64 t, %1; cvt.u32.u64 %0, t; }" : "=r"(a) : "l"(p));
    return a;
}
__device__ __forceinline__ float rna_tf32(float x) {
    uint32_t u;
    asm("cvt.rna.tf32.f32 %0, %1;" : "=r"(u) : "f"(x));
    return __uint_as_float(u);
}
__device__ __forceinline__ uint32_t pkh2(float a, float b) {
    __half2 h = __floats2half2_rn(a, b);
    return *(uint32_t*)&h;
}
#define CP_ASYNC16(dst, src) \
    asm volatile("cp.async.cg.shared.global [%0], [%1], 16;" :: "r"(dst), "l"(src))
#define CP_COMMIT() asm volatile("cp.async.commit_group;")

__device__ __forceinline__ void mma_tf32(float* d, const uint32_t* a, const uint32_t* b) {
    asm volatile(
        "mma.sync.aligned.m16n8k8.row.col.f32.tf32.tf32.f32 "
        "{%0,%1,%2,%3}, {%4,%5,%6,%7}, {%8,%9}, {%0,%1,%2,%3};"
        : "+f"(d[0]), "+f"(d[1]), "+f"(d[2]), "+f"(d[3])
        : "r"(a[0]), "r"(a[1]), "r"(a[2]), "r"(a[3]), "r"(b[0]), "r"(b[1]));
}
__device__ __forceinline__ void mma_f16(float* d, const uint32_t* a, const uint32_t* b) {
    asm volatile(
        "mma.sync.aligned.m16n8k16.row.col.f32.f16.f16.f32 "
        "{%0,%1,%2,%3}, {%4,%5,%6,%7}, {%8,%9}, {%0,%1,%2,%3};"
        : "+f"(d[0]), "+f"(d[1]), "+f"(d[2]), "+f"(d[3])
        : "r"(a[0]), "r"(a[1]), "r"(a[2]), "r"(a[3]), "r"(b[0]), "r"(b[1]));
}

// fast exp on the FMA pipe (no MUFU)
__device__ __forceinline__ float fexp(float x) {
    x = fmaxf(x, -80.0f);
    float y = x * 1.4426950408889634f;
    int   n = __float2int_rn(y);
    float f = y - (float)n;
    float p = 1.33335581e-3f;
    p = fmaf(p, f, 9.61812911e-3f);
    p = fmaf(p, f, 5.55041087e-2f);
    p = fmaf(p, f, 2.40226507e-1f);
    p = fmaf(p, f, 6.93147181e-1f);
    p = fmaf(p, f, 1.0f);
    return p * __int_as_float((n + 127) << 23);
}

extern __shared__ float dynsm[];

// ---------------------------------------------------------------------------
// fp16 GEMM: C[M,N] = Af x Bf^T + bias. Fragments pre-packed (half, RN).
// CTA 128x128, 4 warps (64x64 each), BK=64 (4 k16-atoms/stage), 3-stage pipe.
// ---------------------------------------------------------------------------
#define NSTG 3
#define BKA 4                        // k16 atoms per stage (BK = 64)
#define A_STG_BYTES (8 * BKA * 512)  // 8 mi * 4 ka * 32 lanes * 16B = 16KB
#define B_STG_BYTES (16 * BKA * 256) // 16 ni * 4 ka * 32 lanes * 8B = 16KB
#define STG_BYTES (A_STG_BYTES + B_STG_BYTES)
#define GEMM_SMEM (NSTG * STG_BYTES)

__global__ __launch_bounds__(128) void gemm_mma_kernel(
    const void* __restrict__ Af, const void* __restrict__ Bf,
    const float* __restrict__ bias, float* __restrict__ C,
    int M, int N, int K)
{
    const int K16 = K >> 4;
    const int tid = threadIdx.x, lane = tid & 31, w = tid >> 5;
    const int wm = w >> 1, wn = w & 1;

    const int NT = N >> 7;
    const int per = 8 * NT;
    const int gg = blockIdx.x / per, rr = blockIdx.x % per;
    const int mtile = gg * 8 + (rr & 7);
    const int ntile = rr >> 3;

    const char* Ag = (const char*)Af + (size_t)mtile * 8 * K16 * 512;
    const char* Bg = (const char*)Bf + (size_t)ntile * 16 * K16 * 256;

    const uint32_t sb = smem_u32(dynsm);

    auto fill = [&](int s, int kt0) {
        const uint32_t sA = sb + s * STG_BYTES;
        const uint32_t sB = sA + A_STG_BYTES;
        #pragma unroll
        for (int i = 0; i < 8; i++) {
            int c = tid + i * 128;                 // 0..1023 (A: 16KB / 16B)
            int mi = c >> 7, r = c & 127;          // ka = r>>5, ln = r&31
            const char* g = Ag + (((size_t)mi * K16 + kt0 + (r >> 5)) * 32 + (r & 31)) * 16;
            CP_ASYNC16(sA + c * 16, g);
        }
        #pragma unroll
        for (int i = 0; i < 8; i++) {
            int c = tid + i * 128;                 // 0..1023 (B: 16KB / 16B)
            int ni = c >> 6, r = c & 63;           // ka = r>>4, q = r&15
            const char* g = Bg + ((size_t)ni * K16 + kt0 + (r >> 4)) * 256 + (r & 15) * 16;
            CP_ASYNC16(sB + c * 16, g);
        }
        CP_COMMIT();
    };

    float acc[4][8][4];
    #pragma unroll
    for (int a = 0; a < 4; a++)
        #pragma unroll
        for (int b = 0; b < 8; b++)
            #pragma unroll
            for (int e = 0; e < 4; e++) acc[a][b][e] = 0.0f;

    const int NITER = K16 / BKA;
    #pragma unroll
    for (int s = 0; s < NSTG; s++) fill(s, s * BKA);

    char* smp = (char*)dynsm;
    for (int it = 0; it < NITER; it++) {
        const int s = it % NSTG;
        char* sA = smp + s * STG_BYTES;
        char* sB = sA + A_STG_BYTES;

        asm volatile("cp.async.wait_group %0;" :: "n"(NSTG - 1));
        __syncthreads();

        #pragma unroll
        for (int ki = 0; ki < BKA; ki++) {
            uint32_t afr[4][4];
            #pragma unroll
            for (int a = 0; a < 4; a++) {
                uint4 v = *(const uint4*)(sA + (((wm * 4 + a) * BKA + ki) * 32 + lane) * 16);
                afr[a][0] = v.x; afr[a][1] = v.y; afr[a][2] = v.z; afr[a][3] = v.w;
            }
            uint32_t bfr[8][2];
            #pragma unroll
            for (int b = 0; b < 8; b++) {
                uint2 v = *(const uint2*)(sB + (((wn * 8 + b) * BKA + ki) * 32 + lane) * 8);
                bfr[b][0] = v.x; bfr[b][1] = v.y;
            }
            #pragma unroll
            for (int a = 0; a < 4; a++)
                #pragma unroll
                for (int b = 0; b < 8; b++)
                    mma_f16(acc[a][b], afr[a], bfr[b]);
        }
        __syncthreads();

        if (it + NSTG < NITER) fill(s, (it + NSTG) * BKA);
        else CP_COMMIT();
    }

    const size_t row0 = (size_t)mtile * 128 + wm * 64 + (lane >> 2);
    const int col0 = ntile * 128 + wn * 64 + (lane & 3) * 2;
    #pragma unroll
    for (int a = 0; a < 4; a++) {
        #pragma unroll
        for (int b = 0; b < 8; b++) {
            int c = col0 + b * 8;
            float2 bv = *(const float2*)(bias + c);
            size_t r = row0 + a * 16;
            float2 o0; o0.x = acc[a][b][0] + bv.x; o0.y = acc[a][b][1] + bv.y;
            *(float2*)(C + r * N + c) = o0;
            float2 o1; o1.x = acc[a][b][2] + bv.x; o1.y = acc[a][b][3] + bv.y;
            *(float2*)(C + (r + 8) * N + c) = o1;
        }
    }
}

// ---------------------------------------------------------------------------
// prep: fragmentize to half (RN)
// ---------------------------------------------------------------------------
// A-frag from row-major src[M][K]; block 128, grid (K/32, M/32)
__global__ __launch_bounds__(128) void frag_a_kernel(
    const float* __restrict__ src, __half* __restrict__ dst, int K)
{
    __shared__ float t[32][33];
    const int k0 = blockIdx.x * 32, m0 = blockIdx.y * 32;
    const int tid = threadIdx.x;
    #pragma unroll
    for (int i = 0; i < 8; i++) {
        int idx = tid + i * 128;
        int r = idx >> 5, c = idx & 31;
        t[r][c] = src[(size_t)(m0 + r) * K + k0 + c];
    }
    __syncthreads();
    const int w = tid >> 5, lane = tid & 31;
    const int mi_l = w >> 1, ki_l = w & 1;
    const int r0 = mi_l * 16 + (lane >> 2);
    const int c0 = ki_l * 16 + (lane & 3) * 2;
    uint4 u;
    u.x = pkh2(t[r0][c0],         t[r0][c0 + 1]);
    u.y = pkh2(t[r0 + 8][c0],     t[r0 + 8][c0 + 1]);
    u.z = pkh2(t[r0][c0 + 8],     t[r0][c0 + 9]);
    u.w = pkh2(t[r0 + 8][c0 + 8], t[r0 + 8][c0 + 9]);
    ((uint4*)dst)[((size_t)((m0 >> 4) + mi_l) * (K >> 4) + (k0 >> 4) + ki_l) * 32 + lane] = u;
}

// B-frag from row-major src[K][N]; block 256, grid (N/32, K/32)
__global__ __launch_bounds__(256) void frag_b_kernel(
    const float* __restrict__ src, __half* __restrict__ dst, int K, int N)
{
    __shared__ float t[32][33];
    const int n0 = blockIdx.x * 32, k0 = blockIdx.y * 32;
    const int tid = threadIdx.x;
    #pragma unroll
    for (int i = 0; i < 4; i++) {
        int r = (tid >> 5) + i * 8;
        t[r][tid & 31] = src[(size_t)(k0 + r) * N + n0 + (tid & 31)];
    }
    __syncthreads();
    const int w = tid >> 5, lane = tid & 31;
    const int ni_l = w >> 1, ki_l = w & 1;
    const int n = ni_l * 8 + (lane >> 2);
    const int k = ki_l * 16 + (lane & 3) * 2;
    uint2 u;
    u.x = pkh2(t[k][n],     t[k + 1][n]);
    u.y = pkh2(t[k + 8][n], t[k + 9][n]);
    ((uint2*)dst)[((size_t)((n0 >> 3) + ni_l) * (K >> 4) + (k0 >> 4) + ki_l) * 32 + lane] = u;
}

// ---------------------------------------------------------------------------
// Flash attention on tensor cores (tf32) + FFMA exp. Epilogue -> half A-frag.
// ---------------------------------------------------------------------------
#define F_KF   0
#define F_VF   8192
#define F_PF   16384
#define F_SAL  (F_PF + 4*16*68)
#define FLASH2_SMEM_FLOATS (F_SAL + 64 + 16)
#define QS_STR 132

__global__ __launch_bounds__(128) void flash_mma_kernel(
    const float* __restrict__ qkv, const float* __restrict__ alibi,
    const int* __restrict__ amask, __half* __restrict__ attn_out)
{
    const int qt = blockIdx.x, h = blockIdx.y, b = blockIdx.z;
    const int qb = qt * 64;
    const int tid = threadIdx.x, lane = tid & 31, w = tid >> 5;

    float* sm = dynsm;
    float* Kf = sm + F_KF;
    float* Vf = sm + F_VF;
    float* Pf = sm + F_PF + w * 16 * 68;
    float* sAl = sm + F_SAL;

    const size_t row_stride = (size_t)NHh * 384;
    const size_t qkv_b = (size_t)b * Ss * row_stride + (size_t)h * 384;
    const float* alib = alibi + ((size_t)b * NHh + h) * Ss;
    const int* amk = amask + (size_t)b * Ss;
    const float SCALE = 0.08838834764831845f;

    {
        const float* Qg = qkv + qkv_b + (size_t)qb * row_stride;
        #pragma unroll
        for (int i = 0; i < 16; i++) {
            int u = i * 128 + tid;
            int r = u >> 5, c4 = u & 31;
            float4 v = *(const float4*)(Qg + (size_t)r * row_stride + c4 * 4);
            v.x = rna_tf32(v.x * SCALE); v.y = rna_tf32(v.y * SCALE);
            v.z = rna_tf32(v.z * SCALE); v.w = rna_tf32(v.w * SCALE);
            *(float4*)(sm + r * QS_STR + c4 * 4) = v;
        }
    }
    __syncthreads();

    uint32_t qf[16][4];
    {
        const int r0 = w * 16 + (lane >> 2), c = lane & 3;
        #pragma unroll
        for (int ka = 0; ka < 16; ka++) {
            qf[ka][0] = __float_as_uint(sm[r0 * QS_STR + ka * 8 + c]);
            qf[ka][1] = __float_as_uint(sm[(r0 + 8) * QS_STR + ka * 8 + c]);
            qf[ka][2] = __float_as_uint(sm[r0 * QS_STR + ka * 8 + c + 4]);
            qf[ka][3] = __float_as_uint(sm[(r0 + 8) * QS_STR + ka * 8 + c + 4]);
        }
    }

    float m0 = -1e29f, m1 = -1e29f, l0 = 0.0f, l1 = 0.0f;
    float acc[16][4];
    #pragma unroll
    for (int na = 0; na < 16; na++)
        #pragma unroll
        for (int e = 0; e < 4; e++) acc[na][e] = 0.0f;

    const int qg0 = qb + w * 16 + (lane >> 2);
    const int qg1 = qg0 + 8;

    for (int kt = 0; kt <= qt; kt++) {
        const int kb = kt * 64;
        const float* Kg = qkv + qkv_b + (size_t)kb * row_stride + 128;
        const float* Vg = Kg + 128;

        __syncthreads();

        #pragma unroll
        for (int i = 0; i < 8; i++) {
            int u = i * 128 + tid;
            int k = u & 63, dg = u >> 6;
            const float* rp = Kg + (size_t)k * row_stride + dg * 8;
            float4 a4 = *(const float4*)rp;
            float4 b4 = *(const float4*)(rp + 4);
            float* dst = Kf + (((k >> 3) * 16 + dg) * 32 + (k & 7) * 4) * 2;
            ((float2*)dst)[0] = make_float2(rna_tf32(a4.x), rna_tf32(b4.x));
            ((float2*)dst)[1] = make_float2(rna_tf32(a4.y), rna_tf32(b4.y));
            ((float2*)dst)[2] = make_float2(rna_tf32(a4.z), rna_tf32(b4.z));
            ((float2*)dst)[3] = make_float2(rna_tf32(a4.w), rna_tf32(b4.w));
        }
        #pragma unroll
        for (int i = 0; i < 8; i++) {
            int u = i * 128 + tid;
            int k = u & 63, dg = u >> 6;
            const float* rp = Vg + (size_t)k * row_stride + dg * 8;
            float4 a4 = *(const float4*)rp;
            float4 b4 = *(const float4*)(rp + 4);
            const int e = (k & 7) >> 2;
            float* base = Vf + ((dg * 8 + (k >> 3)) * 32 + (k & 3)) * 2 + e;
            base[0 * 8] = rna_tf32(a4.x); base[1 * 8] = rna_tf32(a4.y);
            base[2 * 8] = rna_tf32(a4.z); base[3 * 8] = rna_tf32(a4.w);
            base[4 * 8] = rna_tf32(b4.x); base[5 * 8] = rna_tf32(b4.y);
            base[6 * 8] = rna_tf32(b4.z); base[7 * 8] = rna_tf32(b4.w);
        }
        if (tid < 64) {
            int kg = kb + tid;
            sAl[tid] = (amk[kg] > 0) ? alib[kg] : -1e30f;
        }
        __syncthreads();

        float sfr[8][4];
        #pragma unroll
        for (int na = 0; na < 8; na++)
            #pragma unroll
            for (int e = 0; e < 4; e++) sfr[na][e] = 0.0f;

        #pragma unroll
        for (int ka = 0; ka < 16; ka++) {
            #pragma unroll
            for (int na = 0; na < 8; na++) {
                const uint32_t* b2 = (const uint32_t*)(Kf + ((na * 16 + ka) * 32 + lane) * 2);
                mma_tf32(sfr[na], qf[ka], b2);
            }
        }

        const bool diag = (kt == qt);
        float tm0 = -1e30f, tm1 = -1e30f;
        #pragma unroll
        for (int na = 0; na < 8; na++) {
            int c0 = na * 8 + (lane & 3) * 2;
            int kg0 = kb + c0;
            float al0 = sAl[c0], al1 = sAl[c0 + 1];
            if (diag) {
                sfr[na][0] = (kg0     <= qg0) ? sfr[na][0] + al0 : -1e30f;
                sfr[na][1] = (kg0 + 1 <= qg0) ? sfr[na][1] + al1 : -1e30f;
                sfr[na][2] = (kg0     <= qg1) ? sfr[na][2] + al0 : -1e30f;
                sfr[na][3] = (kg0 + 1 <= qg1) ? sfr[na][3] + al1 : -1e30f;
            } else {
                sfr[na][0] += al0; sfr[na][1] += al1;
                sfr[na][2] += al0; sfr[na][3] += al1;
            }
            tm0 = fmaxf(tm0, fmaxf(sfr[na][0], sfr[na][1]));
            tm1 = fmaxf(tm1, fmaxf(sfr[na][2], sfr[na][3]));
        }
        tm0 = fmaxf(tm0, __shfl_xor_sync(0xffffffffu, tm0, 1));
        tm0 = fmaxf(tm0, __shfl_xor_sync(0xffffffffu, tm0, 2));
        tm1 = fmaxf(tm1, __shfl_xor_sync(0xffffffffu, tm1, 1));
        tm1 = fmaxf(tm1, __shfl_xor_sync(0xffffffffu, tm1, 2));

        float mn0 = fmaxf(m0, tm0), mn1 = fmaxf(m1, tm1);
        float corr0 = fexp(m0 - mn0), corr1 = fexp(m1 - mn1);

        float rs0 = 0.0f, rs1 = 0.0f;
        const int r0l = lane >> 2, cc = (lane & 3) * 2;
        #pragma unroll
        for (int na = 0; na < 8; na++) {
            float p0 = fexp(sfr[na][0] - mn0);
            float p1 = fexp(sfr[na][1] - mn0);
            float p2 = fexp(sfr[na][2] - mn1);
            float p3 = fexp(sfr[na][3] - mn1);
            rs0 += p0 + p1; rs1 += p2 + p3;
            *(float2*)(Pf + r0l * 68 + na * 8 + cc)       = make_float2(rna_tf32(p0), rna_tf32(p1));
            *(float2*)(Pf + (r0l + 8) * 68 + na * 8 + cc) = make_float2(rna_tf32(p2), rna_tf32(p3));
        }
        rs0 += __shfl_xor_sync(0xffffffffu, rs0, 1);
        rs0 += __shfl_xor_sync(0xffffffffu, rs0, 2);
        rs1 += __shfl_xor_sync(0xffffffffu, rs1, 1);
        rs1 += __shfl_xor_sync(0xffffffffu, rs1, 2);
        l0 = l0 * corr0 + rs0;  m0 = mn0;
        l1 = l1 * corr1 + rs1;  m1 = mn1;
        #pragma unroll
        for (int na = 0; na < 16; na++) {
            acc[na][0] *= corr0; acc[na][1] *= corr0;
            acc[na][2] *= corr1; acc[na][3] *= corr1;
        }
        __syncwarp();

        const int c = lane & 3;
        #pragma unroll
        for (int ka = 0; ka < 8; ka++) {
            uint32_t pa[4];
            pa[0] = __float_as_uint(Pf[r0l * 68 + ka * 8 + c]);
            pa[1] = __float_as_uint(Pf[(r0l + 8) * 68 + ka * 8 + c]);
            pa[2] = __float_as_uint(Pf[r0l * 68 + ka * 8 + c + 4]);
            pa[3] = __float_as_uint(Pf[(r0l + 8) * 68 + ka * 8 + c + 4]);
            #pragma unroll
            for (int na = 0; na < 16; na++) {
                const uint32_t* b2 = (const uint32_t*)(Vf + ((na * 8 + ka) * 32 + lane) * 2);
                mma_tf32(acc[na], pa, b2);
            }
        }
    }

    // epilogue: O/l -> SMEM (C layout) -> half A-frag (m16n8k16) -> gmem
    __syncthreads();
    {
        float inv0 = 1.0f / fmaxf(l0, 1e-30f);
        float inv1 = 1.0f / fmaxf(l1, 1e-30f);
        int r0 = w * 16 + (lane >> 2);
        #pragma unroll
        for (int na = 0; na < 16; na++) {
            int cc = na * 8 + (lane & 3) * 2;
            *(float2*)(sm + r0 * QS_STR + cc)       = make_float2(acc[na][0] * inv0, acc[na][1] * inv0);
            *(float2*)(sm + (r0 + 8) * QS_STR + cc) = make_float2(acc[na][2] * inv1, acc[na][3] * inv1);
        }
    }
    __syncwarp();
    {
        int r0 = w * 16 + (lane >> 2);
        int c2 = (lane & 3) * 2;
        size_t mi = (size_t)(b * Ss + qb + w * 16) >> 4;
        uint4* ao = (uint4*)attn_out;
        #pragma unroll
        for (int ka = 0; ka < 8; ka++) {          // K16 atoms of head dim (128/16)
            int cb = ka * 16;
            uint4 u;
            u.x = pkh2(sm[r0 * QS_STR + cb + c2],           sm[r0 * QS_STR + cb + c2 + 1]);
            u.y = pkh2(sm[(r0 + 8) * QS_STR + cb + c2],     sm[(r0 + 8) * QS_STR + cb + c2 + 1]);
            u.z = pkh2(sm[r0 * QS_STR + cb + 8 + c2],       sm[r0 * QS_STR + cb + 9 + c2]);
            u.w = pkh2(sm[(r0 + 8) * QS_STR + cb + 8 + c2], sm[(r0 + 8) * QS_STR + cb + 9 + c2]);
            ao[(mi * 256 + (size_t)h * 8 + ka) * 32 + lane] = u;
        }
    }
}

// ---------------------------------------------------------------------------
extern "C" void kernel_launch(void* const* d_in, const int* in_sizes, int n_in,
                              void* d_out, int out_size)
{
    const float* hidden = (const float*)d_in[0];
    const float* alibi  = (const float*)d_in[1];
    const float* w_qkv  = (const float*)d_in[2];
    const float* b_qkv  = (const float*)d_in[3];
    const float* w_out  = (const float*)d_in[4];
    const float* b_out  = (const float*)d_in[5];
    const int*   amask  = (const int*)d_in[6];
    float* out = (float*)d_out;

    float *qkv;
    __half *attn, *hid, *w1t, *w2t;
    cudaGetSymbolAddress((void**)&qkv,  g_qkv);
    cudaGetSymbolAddress((void**)&attn, g_attn);
    cudaGetSymbolAddress((void**)&hid,  g_hid);
    cudaGetSymbolAddress((void**)&w1t,  g_w1t);
    cudaGetSymbolAddress((void**)&w2t,  g_w2t);

    cudaFuncSetAttribute(gemm_mma_kernel,
                         cudaFuncAttributeMaxDynamicSharedMemorySize, GEMM_SMEM);
    const int flash_smem = FLASH2_SMEM_FLOATS * (int)sizeof(float);
    cudaFuncSetAttribute(flash_mma_kernel,
                         cudaFuncAttributeMaxDynamicSharedMemorySize, flash_smem);

    // prep: fragmentize to half
    frag_a_kernel<<<dim3(Hh / 32, Mm / 32), 128>>>(hidden, hid, Hh);
    frag_b_kernel<<<dim3(QKVN / 32, Hh / 32), 256>>>(w_qkv, w1t, Hh, QKVN);
    frag_b_kernel<<<dim3(Hh / 32, Hh / 32), 256>>>(w_out, w2t, Hh, Hh);

    // 1) QKV projection (fp16 tensor cores)
    gemm_mma_kernel<<<(Mm / 128) * (QKVN / 128), 128, GEMM_SMEM>>>(
        hid, w1t, b_qkv, qkv, Mm, QKVN, Hh);

    // 2) flash attention (tf32 tensor cores + FFMA exp)
    flash_mma_kernel<<<dim3(Ss / 64, NHh, Bb), 128, flash_smem>>>(
        qkv, alibi, amask, attn);

    // 3) output projection (fp16 tensor cores)
    gemm_mma_kernel<<<(Mm / 128) * (Hh / 128), 128, GEMM_SMEM>>>(
        attn, w2t, b_out, out, Mm, Hh, Hh);
}